// round 17
// baseline (speedup 1.0000x reference)
#include <cuda_runtime.h>

#define PI_F 3.14159265358979323846f
#define RSQRT2 0.70710678118654752440f
#define BMAX 65536

__device__ float4 g_h[BMAX];   // tanh(x.pre_w^T + b)*pi per row
__device__ float4 g_z[BMAX];   // circuit expectation values per row

// ======================= Kernel A: h = tanh(x @ pre_w^T + b)*pi ==========
// 128 threads, 4 rows/warp, 16 rows/block, grid = B/16.
__global__ __launch_bounds__(128, 10) void dots_kernel(
    const float* __restrict__ x,       // [B,1024]
    const float* __restrict__ pre_w,   // [4,1024]
    const float* __restrict__ pre_b,   // [4]
    int B)
{
    const int tid  = threadIdx.x;
    const int warp = tid >> 5;
    const int lane = tid & 31;
    const unsigned FULL = 0xffffffffu;

    const int r0 = blockIdx.x * 16 + warp * 4;
    if (r0 + 3 >= B) return;

    const float4* pw4 = (const float4*)pre_w;   // pw4[q*256 + idx]
    const float4* xr0 = (const float4*)(x + (size_t)r0 * 1024);

    float v[16];                                 // v[r*4+q]
    #pragma unroll
    for (int i = 0; i < 16; i++) v[i] = 0.0f;

    #pragma unroll
    for (int it = 0; it < 8; it++) {
        const int idx = it * 32 + lane;
        float4 w0 = __ldg(&pw4[0*256 + idx]);
        float4 w1 = __ldg(&pw4[1*256 + idx]);
        float4 w2 = __ldg(&pw4[2*256 + idx]);
        float4 w3 = __ldg(&pw4[3*256 + idx]);
        #pragma unroll
        for (int r = 0; r < 4; r++) {
            float4 xv = __ldcs(&xr0[(size_t)r * 256 + idx]);
            v[r*4+0] += xv.x*w0.x + xv.y*w0.y + xv.z*w0.z + xv.w*w0.w;
            v[r*4+1] += xv.x*w1.x + xv.y*w1.y + xv.z*w1.z + xv.w*w1.w;
            v[r*4+2] += xv.x*w2.x + xv.y*w2.y + xv.z*w2.z + xv.w*w2.w;
            v[r*4+3] += xv.x*w3.x + xv.y*w3.y + xv.z*w3.z + xv.w*w3.w;
        }
    }

    // distributing reduce over 16 values: levels xor 16,8,4,2 route values,
    // final xor-1 level completes the sum over lane bit 0.
    // Lane l ends with S[l>>1] (even/odd lanes duplicate).
    #pragma unroll
    for (int i = 0; i < 8; i++) {
        float send = (lane & 16) ? v[i] : v[i+8];
        float recv = __shfl_xor_sync(FULL, send, 16);
        v[i] = ((lane & 16) ? v[i+8] : v[i]) + recv;
    }
    #pragma unroll
    for (int i = 0; i < 4; i++) {
        float send = (lane & 8) ? v[i] : v[i+4];
        float recv = __shfl_xor_sync(FULL, send, 8);
        v[i] = ((lane & 8) ? v[i+4] : v[i]) + recv;
    }
    #pragma unroll
    for (int i = 0; i < 2; i++) {
        float send = (lane & 4) ? v[i] : v[i+2];
        float recv = __shfl_xor_sync(FULL, send, 4);
        v[i] = ((lane & 4) ? v[i+2] : v[i]) + recv;
    }
    {
        float send = (lane & 2) ? v[0] : v[1];
        float recv = __shfl_xor_sync(FULL, send, 2);
        v[0] = ((lane & 2) ? v[1] : v[0]) + recv;
    }
    v[0] += __shfl_xor_sync(FULL, v[0], 1);   // sum over lane bit 0

    // even lanes: S for row r0 + (lane>>3), qubit (lane>>1)&3
    if (!(lane & 1)) {
        const int r = lane >> 3;
        const int q = (lane >> 1) & 3;
        float h = tanhf(v[0] + __ldg(&pre_b[q])) * PI_F;
        ((float*)g_h)[(size_t)(r0 + r) * 4 + q] = h;
    }
}

// ======================= Kernel C: z = circuit(h) ========================
__global__ __launch_bounds__(256) void circuit_kernel(
    const float* __restrict__ qw,      // [1,4,3]
    int B)
{
    __shared__ float usm[4][8];
    const int tid = threadIdx.x;

    if (tid < 4) {
        float phi = qw[tid * 3 + 0];
        float th  = qw[tid * 3 + 1];
        float om  = qw[tid * 3 + 2];
        float spo, cpo, spm, cpm, st, ct;
        sincosf(0.5f * (phi + om), &spo, &cpo);
        sincosf(0.5f * (phi - om), &spm, &cpm);
        sincosf(0.5f * th,         &st,  &ct);
        usm[tid][0] =  cpo * ct;  usm[tid][1] = -spo * ct;  // u00
        usm[tid][2] = -cpm * st;  usm[tid][3] = -spm * st;  // u01
        usm[tid][4] =  cpm * st;  usm[tid][5] = -spm * st;  // u10
        usm[tid][6] =  cpo * ct;  usm[tid][7] =  spo * ct;  // u11
    }
    __syncthreads();

    const int r = blockIdx.x * 256 + tid;
    if (r >= B) return;

    float4 hv = g_h[r];
    float hq[4] = {hv.x, hv.y, hv.z, hv.w};

    float vr[4][2], vi[4][2];
    #pragma unroll
    for (int q = 0; q < 4; q++) {
        float f = hq[q];
        float sa, ca; sincosf(0.5f * atanf(f), &sa, &ca);
        float A  = (ca - sa) * RSQRT2;
        float Bv = (ca + sa) * RSQRT2;
        float sb, cb; sincosf(0.5f * atanf(f * f), &sb, &cb);
        vr[q][0] = A  * cb;  vi[q][0] = -A  * sb;
        vr[q][1] = Bv * cb;  vi[q][1] =  Bv * sb;
    }
    float c2r[4], c2i[4];
    #pragma unroll
    for (int j = 0; j < 4; j++) {
        int b3 = (j >> 1) & 1, b2 = j & 1;
        c2r[j] = vr[0][b3]*vr[1][b2] - vi[0][b3]*vi[1][b2];
        c2i[j] = vr[0][b3]*vi[1][b2] + vi[0][b3]*vr[1][b2];
    }
    float c3r[8], c3i[8];
    #pragma unroll
    for (int j = 0; j < 8; j++) {
        int hi = j >> 1, b1 = j & 1;
        c3r[j] = c2r[hi]*vr[2][b1] - c2i[hi]*vi[2][b1];
        c3i[j] = c2r[hi]*vi[2][b1] + c2i[hi]*vr[2][b1];
    }
    float pr[16], pim[16];
    #pragma unroll
    for (int j = 0; j < 16; j++) {
        int hi = j >> 1, b0 = j & 1;
        pr[j]  = c3r[hi]*vr[3][b0] - c3i[hi]*vi[3][b0];
        pim[j] = c3r[hi]*vi[3][b0] + c3i[hi]*vr[3][b0];
    }
    float tr[16], ti[16];
    #pragma unroll
    for (int j = 0; j < 16; j++) {
        int xg = j;
        xg ^= (xg & 1) << 3;           // CNOT ring composed
        xg ^= (xg >> 1) & 1;
        xg ^= ((xg >> 2) & 1) << 1;
        xg ^= ((xg >> 3) & 1) << 2;
        tr[j] = pr[xg];
        ti[j] = pim[xg];
    }
    #pragma unroll
    for (int q = 0; q < 4; q++) {
        const float u00r = usm[q][0], u00i = usm[q][1];
        const float u01r = usm[q][2], u01i = usm[q][3];
        const float u10r = usm[q][4], u10i = usm[q][5];
        const float u11r = usm[q][6], u11i = usm[q][7];
        const int mask = 8 >> q;
        #pragma unroll
        for (int j0 = 0; j0 < 16; j0++) {
            if (j0 & mask) continue;
            const int j1 = j0 | mask;
            float ar = tr[j0], ai = ti[j0];
            float br = tr[j1], bi = ti[j1];
            tr[j0] = u00r*ar - u00i*ai + u01r*br - u01i*bi;
            ti[j0] = u00r*ai + u00i*ar + u01r*bi + u01i*br;
            tr[j1] = u10r*ar - u10i*ai + u11r*br - u11i*bi;
            ti[j1] = u10r*ai + u10i*ar + u11r*bi + u11i*br;
        }
    }
    float z0 = 0.f, z1 = 0.f, z2 = 0.f, z3 = 0.f;
    #pragma unroll
    for (int j = 0; j < 16; j++) {
        float p = tr[j]*tr[j] + ti[j]*ti[j];
        z0 += (j & 8) ? -p : p;
        z1 += (j & 4) ? -p : p;
        z2 += (j & 2) ? -p : p;
        z3 += (j & 1) ? -p : p;
    }
    g_z[r] = make_float4(z0, z1, z2, z3);
}

// ======================= Kernel B: out = z @ post_w^T + post_b ===========
// 128 threads, 4 rows/warp, 16 rows/block, grid = B/16.
__global__ __launch_bounds__(128, 10) void post_kernel(
    const float* __restrict__ post_w,  // [1024,4]
    const float* __restrict__ post_b,  // [1024]
    float* __restrict__ out,           // [B,1024]
    int B)
{
    const int tid  = threadIdx.x;
    const int warp = tid >> 5;
    const int lane = tid & 31;

    const int r0 = blockIdx.x * 16 + warp * 4;
    if (r0 + 3 >= B) return;

    const float4* pwg4 = (const float4*)post_w;   // pwg4[j] = post_w[j][0..3]
    const float4* pbg4 = (const float4*)post_b;

    float4 zv0 = __ldg(&g_z[r0 + 0]);
    float4 zv1 = __ldg(&g_z[r0 + 1]);
    float4 zv2 = __ldg(&g_z[r0 + 2]);
    float4 zv3 = __ldg(&g_z[r0 + 3]);

    float4* o0 = (float4*)(out + (size_t)r0 * 1024);
    #pragma unroll
    for (int jt = 0; jt < 8; jt++) {
        const int fi = jt * 32 + lane;            // float4 col index
        float4 ga0 = __ldg(&pwg4[4*fi + 0]);
        float4 ga1 = __ldg(&pwg4[4*fi + 1]);
        float4 ga2 = __ldg(&pwg4[4*fi + 2]);
        float4 ga3 = __ldg(&pwg4[4*fi + 3]);
        float4 bb  = __ldg(&pbg4[fi]);
        float4 o;
        o.x = bb.x + zv0.x*ga0.x + zv0.y*ga0.y + zv0.z*ga0.z + zv0.w*ga0.w;
        o.y = bb.y + zv0.x*ga1.x + zv0.y*ga1.y + zv0.z*ga1.z + zv0.w*ga1.w;
        o.z = bb.z + zv0.x*ga2.x + zv0.y*ga2.y + zv0.z*ga2.z + zv0.w*ga2.w;
        o.w = bb.w + zv0.x*ga3.x + zv0.y*ga3.y + zv0.z*ga3.z + zv0.w*ga3.w;
        __stcs(&o0[fi], o);
        o.x = bb.x + zv1.x*ga0.x + zv1.y*ga0.y + zv1.z*ga0.z + zv1.w*ga0.w;
        o.y = bb.y + zv1.x*ga1.x + zv1.y*ga1.y + zv1.z*ga1.z + zv1.w*ga1.w;
        o.z = bb.z + zv1.x*ga2.x + zv1.y*ga2.y + zv1.z*ga2.z + zv1.w*ga2.w;
        o.w = bb.w + zv1.x*ga3.x + zv1.y*ga3.y + zv1.z*ga3.z + zv1.w*ga3.w;
        __stcs(&o0[256 + fi], o);
        o.x = bb.x + zv2.x*ga0.x + zv2.y*ga0.y + zv2.z*ga0.z + zv2.w*ga0.w;
        o.y = bb.y + zv2.x*ga1.x + zv2.y*ga1.y + zv2.z*ga1.z + zv2.w*ga1.w;
        o.z = bb.z + zv2.x*ga2.x + zv2.y*ga2.y + zv2.z*ga2.z + zv2.w*ga2.w;
        o.w = bb.w + zv2.x*ga3.x + zv2.y*ga3.y + zv2.z*ga3.z + zv2.w*ga3.w;
        __stcs(&o0[512 + fi], o);
        o.x = bb.x + zv3.x*ga0.x + zv3.y*ga0.y + zv3.z*ga0.z + zv3.w*ga0.w;
        o.y = bb.y + zv3.x*ga1.x + zv3.y*ga1.y + zv3.z*ga1.z + zv3.w*ga1.w;
        o.z = bb.z + zv3.x*ga2.x + zv3.y*ga2.y + zv3.z*ga2.z + zv3.w*ga2.w;
        o.w = bb.w + zv3.x*ga3.x + zv3.y*ga3.y + zv3.z*ga3.z + zv3.w*ga3.w;
        __stcs(&o0[768 + fi], o);
    }
}

extern "C" void kernel_launch(void* const* d_in, const int* in_sizes, int n_in,
                              void* d_out, int out_size) {
    const float* x      = (const float*)d_in[0];
    const float* pre_w  = (const float*)d_in[1];
    const float* pre_b  = (const float*)d_in[2];
    const float* qw     = (const float*)d_in[3];
    const float* post_w = (const float*)d_in[4];
    const float* post_b = (const float*)d_in[5];
    float* out = (float*)d_out;

    int B = in_sizes[0] / 1024;
    if (B > BMAX) B = BMAX;

    dots_kernel<<<(B + 15) / 16, 128>>>(x, pre_w, pre_b, B);
    circuit_kernel<<<(B + 255) / 256, 256>>>(qw, B);
    post_kernel<<<(B + 15) / 16, 128>>>(post_w, post_b, out, B);
}